// round 1
// baseline (speedup 1.0000x reference)
#include <cuda_runtime.h>
#include <cuda_bf16.h>
#include <cstdint>

// Problem constants (fixed by the dataset): N=1,000,000 points, C=64 channels, K=64 grid
#define KGRID 64
#define NCELLS (KGRID * KGRID * KGRID)   // 262144
#define NMAX 1000064

// Scratch in __device__ globals (no allocation allowed)
__device__ int g_counts[NCELLS];
__device__ int g_pidx[NMAX];

// ---------------------------------------------------------------------------
// Kernel 1: compute flat voxel index per point + per-cell counts
// ---------------------------------------------------------------------------
__global__ void idx_kernel(const float* __restrict__ points, int n) {
    int i = blockIdx.x * blockDim.x + threadIdx.x;
    if (i >= n) return;
    float x = points[3 * i + 0];
    float y = points[3 * i + 1];
    float z = points[3 * i + 2];
    // match reference: floor((p+1)*k/2), clip to [0, k-1]
    int ix = (int)floorf((x + 1.0f) * (KGRID * 0.5f));
    int iy = (int)floorf((y + 1.0f) * (KGRID * 0.5f));
    int iz = (int)floorf((z + 1.0f) * (KGRID * 0.5f));
    ix = min(max(ix, 0), KGRID - 1);
    iy = min(max(iy, 0), KGRID - 1);
    iz = min(max(iz, 0), KGRID - 1);
    int idx = ix * (KGRID * KGRID) + iy * KGRID + iz;
    g_pidx[i] = idx;
    atomicAdd(&g_counts[idx], 1);
}

// ---------------------------------------------------------------------------
// Kernel 2: scatter-add features into the sums array (d_out) with vector RED.
// 16 threads cooperate on one point: thread q handles float4 chunk q of 16.
// Feature loads are fully coalesced (16 x 16B = one 256B row per point).
// ---------------------------------------------------------------------------
__global__ void scatter_kernel(const float4* __restrict__ feat4,
                               float* __restrict__ out, int n) {
    int gid = blockIdx.x * blockDim.x + threadIdx.x;
    int total = n * 16;
    if (gid >= total) return;
    int pt = gid >> 4;
    int q  = gid & 15;
    int cell = g_pidx[pt];             // broadcast load within the 16-group
    float4 v = feat4[(size_t)pt * 16 + q];
    float* dst = out + (size_t)cell * 64 + q * 4;
    // vector reduction: one L2 atomic op per 16 bytes
    asm volatile("red.global.add.v4.f32 [%0], {%1, %2, %3, %4};"
                 :: "l"(dst), "f"(v.x), "f"(v.y), "f"(v.z), "f"(v.w)
                 : "memory");
}

// ---------------------------------------------------------------------------
// Kernel 3: divide sums by counts (in place), float4-vectorized.
// ---------------------------------------------------------------------------
__global__ void divide_kernel(float4* __restrict__ out) {
    int gid = blockIdx.x * blockDim.x + threadIdx.x;
    const int total = NCELLS * 16;     // 64 floats per cell = 16 float4
    if (gid >= total) return;
    int cell = gid >> 4;
    int c = g_counts[cell];
    float inv = 1.0f / (float)(c > 0 ? c : 1);
    float4 v = out[gid];
    v.x *= inv; v.y *= inv; v.z *= inv; v.w *= inv;
    out[gid] = v;
}

// ---------------------------------------------------------------------------
// Launcher
// inputs: d_in[0] = point_feat (N*64 f32), d_in[1] = points (N*3 f32),
//         d_in[2] = k (int, =64). out: (64,64,64,64) f32
// ---------------------------------------------------------------------------
extern "C" void kernel_launch(void* const* d_in, const int* in_sizes, int n_in,
                              void* d_out, int out_size) {
    const float*  points = (const float*)d_in[1];
    const float4* feat4  = (const float4*)d_in[0];
    float* out = (float*)d_out;

    int n = in_sizes[1] / 3;   // number of points

    // zero the counts scratch and the output (sums accumulator)
    void* counts_ptr = nullptr;
    cudaGetSymbolAddress(&counts_ptr, g_counts);
    cudaMemsetAsync(counts_ptr, 0, NCELLS * sizeof(int), 0);
    cudaMemsetAsync(d_out, 0, (size_t)NCELLS * 64 * sizeof(float), 0);

    const int T = 256;
    idx_kernel<<<(n + T - 1) / T, T>>>(points, n);
    scatter_kernel<<<((size_t)n * 16 + T - 1) / T, T>>>(feat4, out, n);
    divide_kernel<<<(NCELLS * 16 + T - 1) / T, T>>>((float4*)out);
}

// round 2
// speedup vs baseline: 1.0144x; 1.0144x over previous
#include <cuda_runtime.h>
#include <cuda_bf16.h>
#include <cstdint>

// Problem constants (fixed by the dataset): N=1,000,000 points, C=64 channels, K=64 grid
#define KGRID 64
#define NCELLS (KGRID * KGRID * KGRID)   // 262144
#define NMAX 1000064

// Scratch in __device__ globals (no allocation allowed)
__device__ int g_counts[NCELLS];
__device__ int g_pidx[NMAX];

// ---------------------------------------------------------------------------
// Kernel 1: compute flat voxel index per point + per-cell counts
// ---------------------------------------------------------------------------
__global__ void idx_kernel(const float* __restrict__ points, int n) {
    int i = blockIdx.x * blockDim.x + threadIdx.x;
    if (i >= n) return;
    float x = points[3 * i + 0];
    float y = points[3 * i + 1];
    float z = points[3 * i + 2];
    // match reference: floor((p+1)*k/2), clip to [0, k-1]
    int ix = (int)floorf((x + 1.0f) * (KGRID * 0.5f));
    int iy = (int)floorf((y + 1.0f) * (KGRID * 0.5f));
    int iz = (int)floorf((z + 1.0f) * (KGRID * 0.5f));
    ix = min(max(ix, 0), KGRID - 1);
    iy = min(max(iy, 0), KGRID - 1);
    iz = min(max(iz, 0), KGRID - 1);
    int idx = ix * (KGRID * KGRID) + iy * KGRID + iz;
    g_pidx[i] = idx;
    atomicAdd(&g_counts[idx], 1);
}

// ---------------------------------------------------------------------------
// Kernel 2: scatter-add features into the sums array (d_out) with vector RED.
// 16 threads cooperate on one point: thread q handles float4 chunk q of 16.
// Feature loads are fully coalesced (16 x 16B = one 256B row per point).
// ---------------------------------------------------------------------------
__global__ void scatter_kernel(const float4* __restrict__ feat4,
                               float* __restrict__ out, int n) {
    int gid = blockIdx.x * blockDim.x + threadIdx.x;
    int total = n * 16;
    if (gid >= total) return;
    int pt = gid >> 4;
    int q  = gid & 15;
    int cell = g_pidx[pt];             // broadcast load within the 16-group
    float4 v = feat4[(size_t)pt * 16 + q];
    float* dst = out + (size_t)cell * 64 + q * 4;
    // vector reduction: one L2 atomic op per 16 bytes
    asm volatile("red.global.add.v4.f32 [%0], {%1, %2, %3, %4};"
                 :: "l"(dst), "f"(v.x), "f"(v.y), "f"(v.z), "f"(v.w)
                 : "memory");
}

// ---------------------------------------------------------------------------
// Kernel 3: divide sums by counts (in place), float4-vectorized.
// ---------------------------------------------------------------------------
__global__ void divide_kernel(float4* __restrict__ out) {
    int gid = blockIdx.x * blockDim.x + threadIdx.x;
    const int total = NCELLS * 16;     // 64 floats per cell = 16 float4
    if (gid >= total) return;
    int cell = gid >> 4;
    int c = g_counts[cell];
    float inv = 1.0f / (float)(c > 0 ? c : 1);
    float4 v = out[gid];
    v.x *= inv; v.y *= inv; v.z *= inv; v.w *= inv;
    out[gid] = v;
}

// ---------------------------------------------------------------------------
// Launcher
// inputs: d_in[0] = point_feat (N*64 f32), d_in[1] = points (N*3 f32),
//         d_in[2] = k (int, =64). out: (64,64,64,64) f32
// ---------------------------------------------------------------------------
extern "C" void kernel_launch(void* const* d_in, const int* in_sizes, int n_in,
                              void* d_out, int out_size) {
    const float*  points = (const float*)d_in[1];
    const float4* feat4  = (const float4*)d_in[0];
    float* out = (float*)d_out;

    int n = in_sizes[1] / 3;   // number of points

    // zero the counts scratch and the output (sums accumulator)
    void* counts_ptr = nullptr;
    cudaGetSymbolAddress(&counts_ptr, g_counts);
    cudaMemsetAsync(counts_ptr, 0, NCELLS * sizeof(int), 0);
    cudaMemsetAsync(d_out, 0, (size_t)NCELLS * 64 * sizeof(float), 0);

    const int T = 256;
    idx_kernel<<<(n + T - 1) / T, T>>>(points, n);
    scatter_kernel<<<((size_t)n * 16 + T - 1) / T, T>>>(feat4, out, n);
    divide_kernel<<<(NCELLS * 16 + T - 1) / T, T>>>((float4*)out);
}